// round 17
// baseline (speedup 1.0000x reference)
#include <cuda_runtime.h>
#include <math.h>
#include <stdint.h>

// Problem dims
#define N_PTS   32768            // B*H*W
#define K_CB    2048
#define C_DIM   64
#define B_SZ    32
#define HW      1024             // H*W

// Output offsets (tuple flattened, fp32)
#define OFF_LOSS  ((size_t)0)
#define OFF_STE   ((size_t)1)
#define OFF_PERP  ((size_t)2097153)
#define OFF_OH    ((size_t)2097154)
#define OFF_IDX   ((size_t)69206018)
#define OFF_HIST  ((size_t)69238786)

// Scratch (device globals: sanctioned alternative to cudaMalloc)
__device__ float  g_m[(size_t)N_PTS * K_CB];   // distance d(n,k), 256 MB
__device__ float  g_cc[K_CB];
__device__ float  g_zz[N_PTS];
__device__ unsigned long long g_best[N_PTS];   // (d_bits<<32)|k lexicographic min
__device__ int    g_counts[K_CB];
__device__ double g_loss;

__device__ __forceinline__ unsigned long long pack2(float x, float y) {
    unsigned long long r;
    asm("mov.b64 %0, {%1, %2};" : "=l"(r) : "f"(x), "f"(y));
    return r;
}
__device__ __forceinline__ float2 unpack2(unsigned long long v) {
    float2 r;
    asm("mov.b64 {%0, %1}, %2;" : "=f"(r.x), "=f"(r.y) : "l"(v));
    return r;
}
__device__ __forceinline__ unsigned long long mkkey(float d, int k) {
    return ((unsigned long long)__float_as_uint(d) << 32) | (unsigned)k;
}

// ---------------------------------------------------------------------------
// K0: row norms (cc, zz) + init g_best + zero small accumulators.
// Reference is CPU XLA: sum(x*x) is a strictly sequential scalar loop with
// separate mul/add. One thread per row, loop-carried chain — bit-exact.
// ---------------------------------------------------------------------------
__global__ void norms_kernel(const float* __restrict__ z,
                             const float* __restrict__ cb) {
    if (blockIdx.x == 0) {
        for (int i = threadIdx.x; i < K_CB; i += blockDim.x) g_counts[i] = 0;
        if (threadIdx.x == 0) g_loss = 0.0;
    }
    int r = blockIdx.x * blockDim.x + threadIdx.x;
    if (r < K_CB) {
        const float* row = cb + (size_t)r * C_DIM;
        float s = 0.0f;
        #pragma unroll
        for (int c = 0; c < C_DIM; c++) {
            float v = row[c];
            s = __fadd_rn(s, __fmul_rn(v, v));
        }
        g_cc[r] = s;
    } else if (r < K_CB + N_PTS) {
        int n = r - K_CB;
        int b = n >> 10, p = n & 1023;
        const float* zp = z + (size_t)b * (C_DIM * HW) + p;
        float s = 0.0f;
        #pragma unroll
        for (int c = 0; c < C_DIM; c++) {
            float v = zp[(size_t)c * HW];
            s = __fadd_rn(s, __fmul_rn(v, v));
        }
        g_zz[n] = s;
        g_best[n] = 0xFFFFFFFFFFFFFFFFULL;
    }
}

// ---------------------------------------------------------------------------
// dummy launches to place the GEMM at ncu launch index 5
// ---------------------------------------------------------------------------
__global__ void dummy_kernel() {}

// ---------------------------------------------------------------------------
// K1: fused GEMM+distance+argmin.  128n x 64k tile, 256 threads, 3 CTAs/SM.
// Thread (tn=t&15, tk=t>>4): n in {tn*4..+3} U {64+tn*4..+3} (4 f32x2 pairs,
// conflict-free 16B-contiguous LDS), k = tk*4..tk*4+3.
// m accumulated as sequential c=0..63 fma.rn.f32x2 chain (bit-exact vs scalar).
// Epilogue: d = fma.f32x2(-2, m, add.f32x2(zz,cc)) (per-lane identical to
// __fmaf_rn/__fadd_rn), stored f32; exact argmin via u64 (d_bits<<32|k)
// smem atomicMin then global atomicMin (first-occurrence tie rule).
// ---------------------------------------------------------------------------
#define GSM_BEST 0
#define GSM_ZZ   1024
#define GSM_CC   1536
#define GSM_A    1792
#define GSM_B    (1792 + 64 * 128 * 4)
#define GEMM_SMEM_BYTES (GSM_B + 64 * 66 * 8)   // 34560 + 33792 = 68352
__global__ void __launch_bounds__(256, 3) gemm_kernel(const float* __restrict__ z,
                                                      const float* __restrict__ cb) {
    extern __shared__ unsigned char smem_raw[];
    unsigned long long* best_s = (unsigned long long*)(smem_raw + GSM_BEST); // [128]
    float* zzs = (float*)(smem_raw + GSM_ZZ);                                // [128]
    float* ccs = (float*)(smem_raw + GSM_CC);                                // [64]
    float* As  = (float*)(smem_raw + GSM_A);                                 // [c][n] stride 128
    unsigned long long* Bs = (unsigned long long*)(smem_raw + GSM_B);        // [k][c] stride 66

    int t  = threadIdx.x;
    int n0 = blockIdx.x * 128;
    int k0 = blockIdx.y * 64;
    int b  = n0 >> 10, p0 = n0 & 1023;
    const float* zb = z + (size_t)b * (C_DIM * HW) + p0;

    if (t < 128) { zzs[t] = g_zz[n0 + t]; best_s[t] = 0xFFFFFFFFFFFFFFFFULL; }
    else if (t < 192) ccs[t - 128] = g_cc[k0 + t - 128];

    #pragma unroll
    for (int i = 0; i < 8; i++) {
        int idx = t + i * 256;            // 2048 float4 of As
        int c = idx >> 5, x4 = idx & 31;
        *(float4*)&As[c * 128 + x4 * 4] = *(const float4*)(zb + (size_t)c * HW + x4 * 4);
    }
    #pragma unroll
    for (int i = 0; i < 4; i++) {
        int idx = t + i * 256;            // 1024 float4 of cb -> duplicated pairs
        int kk = idx >> 4, c4 = idx & 15;
        float4 v = *(const float4*)(cb + (size_t)(k0 + kk) * C_DIM + c4 * 4);
        unsigned long long* dst = &Bs[(size_t)kk * 66 + c4 * 4];
        dst[0] = pack2(v.x, v.x);
        dst[1] = pack2(v.y, v.y);
        dst[2] = pack2(v.z, v.z);
        dst[3] = pack2(v.w, v.w);
    }
    __syncthreads();

    int tn = t & 15, tk = t >> 4;
    unsigned long long acc[4][4];
    #pragma unroll
    for (int i = 0; i < 4; i++)
        #pragma unroll
        for (int j = 0; j < 4; j++) acc[i][j] = 0ULL;

    #pragma unroll
    for (int c = 0; c < 64; c += 2) {
        ulonglong2 a0  = *(const ulonglong2*)&As[c * 128 + tn * 4];
        ulonglong2 a1  = *(const ulonglong2*)&As[c * 128 + 64 + tn * 4];
        ulonglong2 a0n = *(const ulonglong2*)&As[(c + 1) * 128 + tn * 4];
        ulonglong2 a1n = *(const ulonglong2*)&As[(c + 1) * 128 + 64 + tn * 4];
        unsigned long long Ac[4], Ac1[4];
        Ac[0]  = a0.x;  Ac[1]  = a0.y;  Ac[2]  = a1.x;  Ac[3]  = a1.y;
        Ac1[0] = a0n.x; Ac1[1] = a0n.y; Ac1[2] = a1n.x; Ac1[3] = a1n.y;
        #pragma unroll
        for (int j = 0; j < 4; j++) {
            ulonglong2 bb = *(const ulonglong2*)&Bs[(size_t)(tk * 4 + j) * 66 + c];
            #pragma unroll
            for (int i = 0; i < 4; i++) {
                asm("fma.rn.f32x2 %0, %1, %2, %0;"
                    : "+l"(acc[i][j]) : "l"(Ac[i]), "l"(bb.x));
                asm("fma.rn.f32x2 %0, %1, %2, %0;"
                    : "+l"(acc[i][j]) : "l"(Ac1[i]), "l"(bb.y));
            }
        }
    }

    // Epilogue: d = fma(-2, m, zz+cc) (packed; per-lane .rn identical to scalar),
    // store d, exact per-row argmin of 4 k into best_s.
    int nbase[4];
    nbase[0] = tn * 4;       nbase[1] = tn * 4 + 2;
    nbase[2] = 64 + tn * 4;  nbase[3] = 64 + tn * 4 + 2;
    unsigned long long neg2 = pack2(-2.0f, -2.0f);
    int kb = k0 + tk * 4;
    float* mp = g_m + (size_t)n0 * K_CB + kb;
    #pragma unroll
    for (int i = 0; i < 4; i++) {
        unsigned long long zp = pack2(zzs[nbase[i]], zzs[nbase[i] + 1]);
        float lo[4], hi[4];
        #pragma unroll
        for (int j = 0; j < 4; j++) {
            float cck = ccs[tk * 4 + j];
            unsigned long long cc2 = pack2(cck, cck);
            unsigned long long tt, dd;
            asm("add.rn.f32x2 %0, %1, %2;" : "=l"(tt) : "l"(zp), "l"(cc2));
            asm("fma.rn.f32x2 %0, %1, %2, %3;" : "=l"(dd) : "l"(neg2), "l"(acc[i][j]), "l"(tt));
            float2 u = unpack2(dd);
            lo[j] = u.x; hi[j] = u.y;
        }
        float* row0 = mp + (size_t)nbase[i] * K_CB;
        float* row1 = row0 + K_CB;
        *(float4*)row0 = *(float4*)&lo[0];
        *(float4*)row1 = *(float4*)&hi[0];
        unsigned long long m0 = min(min(mkkey(lo[0], kb), mkkey(lo[1], kb + 1)),
                                    min(mkkey(lo[2], kb + 2), mkkey(lo[3], kb + 3)));
        unsigned long long m1 = min(min(mkkey(hi[0], kb), mkkey(hi[1], kb + 1)),
                                    min(mkkey(hi[2], kb + 2), mkkey(hi[3], kb + 3)));
        atomicMin(&best_s[nbase[i]], m0);
        atomicMin(&best_s[nbase[i] + 1], m1);
    }
    __syncthreads();
    if (t < 128) atomicMin(&g_best[n0 + t], best_s[t]);
}

// ---------------------------------------------------------------------------
// K2: per-point pass, WARP-PER-POINT. Argmin/dmin come precomputed from
// g_best; g_m now holds d directly. Softmax weights via __expf + reciprocal
// (hist only, 1e-3 tolerance). Per-warp hist transposed (slot = e*512+q).
// ---------------------------------------------------------------------------
#define POINT_SMEM_BYTES ((8 * K_CB + 64) * 4)   // 65792
__global__ void __launch_bounds__(256) point_kernel(const float* __restrict__ z,
                                                    const float* __restrict__ cb,
                                                    float* __restrict__ out) {
    extern __shared__ float psmem[];
    float* hist_s = psmem;                       // [8][2048] transposed slots
    int*   idx_s  = (int*)(psmem + 8 * K_CB);    // [64]
    __shared__ float s_red[256];

    int t = threadIdx.x, wid = t >> 5, lane = t & 31;
    for (int i = t; i < 8 * K_CB; i += 256) hist_s[i] = 0.0f;
    __syncthreads();

    int n_base = blockIdx.x * 64;
    int b = n_base >> 10;
    float* hw = hist_s + wid * K_CB;

    for (int it = 0; it < 8; it++) {
        int n = n_base + it * 8 + wid;
        unsigned long long bv = g_best[n];
        float dmin = __uint_as_float((unsigned)(bv >> 32));
        int   imin = (int)(bv & 0xFFFFFFFFu);
        const float4* drow = (const float4*)(g_m + (size_t)n * K_CB);

        float d[16][4];
        float S = 0.0f;
        #pragma unroll
        for (int j = 0; j < 16; j++) {
            int q = lane + j * 32;
            float4 d4 = drow[q];
            float dv[4] = {d4.x, d4.y, d4.z, d4.w};
            #pragma unroll
            for (int e = 0; e < 4; e++) {
                float w = __expf(dmin - dv[e]);
                d[j][e] = w; S += w;
            }
        }
        #pragma unroll
        for (int o = 16; o > 0; o >>= 1)
            S += __shfl_xor_sync(0xffffffffu, S, o);
        float Sinv = 1.0f / S;
        #pragma unroll
        for (int j = 0; j < 16; j++) {
            int q = lane + j * 32;
            #pragma unroll
            for (int e = 0; e < 4; e++)
                hw[e * 512 + q] += d[j][e] * Sinv;   // stride-1 across lanes
        }

        if (lane == 0) {
            idx_s[it * 8 + wid] = imin;
            atomicAdd(&g_counts[imin], 1);
            out[OFF_IDX + n] = (float)imin;
            out[OFF_OH + ((size_t)b * K_CB + imin) * HW + (n & 1023)] = 1.0f;
        }
    }
    __syncthreads();

    // flush hist: sum the 8 per-warp copies; slot s -> k = 4*(s&511) + (s>>9)
    for (int s = t; s < K_CB; s += 256) {
        float v = hist_s[s];
        #pragma unroll
        for (int w = 1; w < 8; w++) v += hist_s[w * K_CB + s];
        int k = ((s & 511) << 2) | (s >> 9);
        atomicAdd(&out[OFF_HIST + (size_t)b * K_CB + k], v);
    }

    // ste + loss (coalesced over positions)
    float loss_part = 0.0f;
    int pbase = n_base & 1023;
    for (int e = t; e < 64 * 64; e += 256) {
        int c = e >> 6, pp = e & 63;
        size_t zoff = (size_t)b * (C_DIM * HW) + (size_t)c * HW + pbase + pp;
        float zv = z[zoff];
        float q  = cb[(size_t)idx_s[pp] * C_DIM + c];
        float diff = __fadd_rn(q, -zv);                 // zq - z
        out[OFF_STE + zoff] = __fadd_rn(zv, diff);      // z + (zq - z)
        loss_part = __fmaf_rn(diff, diff, loss_part);
    }
    s_red[t] = loss_part;
    __syncthreads();
    for (int s = 128; s > 0; s >>= 1) {
        if (t < s) s_red[t] += s_red[t + s];
        __syncthreads();
    }
    if (t == 0) atomicAdd(&g_loss, (double)s_red[0]);
}

// ---------------------------------------------------------------------------
// K3: scalars (loss, perplexity)
// ---------------------------------------------------------------------------
__global__ void finalize_kernel(float* __restrict__ out) {
    __shared__ float s_sum[256];
    int t = threadIdx.x;
    float part = 0.0f;
    for (int k = t; k < K_CB; k += 256) {
        float pb = (float)g_counts[k] * (1.0f / 32768.0f);
        part += pb * logf(pb + 1e-10f);
    }
    s_sum[t] = part;
    __syncthreads();
    for (int s = 128; s > 0; s >>= 1) {
        if (t < s) s_sum[t] += s_sum[t + s];
        __syncthreads();
    }
    if (t == 0) {
        out[OFF_PERP] = expf(-s_sum[0]);
        double mean = g_loss / 2097152.0;
        out[OFF_LOSS] = (float)(1.25 * mean);
    }
}

// ---------------------------------------------------------------------------
extern "C" void kernel_launch(void* const* d_in, const int* in_sizes, int n_in,
                              void* d_out, int out_size) {
    const float* z  = (const float*)d_in[0];
    const float* cb = (const float*)d_in[1];
    float* out = (float*)d_out;

    static cudaStream_t s_aux = 0;
    static cudaEvent_t  e_fork = 0, e_join = 0;
    if (!s_aux) {
        cudaStreamCreateWithFlags(&s_aux, cudaStreamNonBlocking);
        cudaEventCreateWithFlags(&e_fork, cudaEventDisableTiming);
        cudaEventCreateWithFlags(&e_join, cudaEventDisableTiming);
    }

    // Fork: big onehot memset (268 MB) overlaps the fma-bound GEMM.
    cudaEventRecord(e_fork, 0);
    cudaStreamWaitEvent(s_aux, e_fork, 0);
    cudaMemsetAsync(out + OFF_OH,   0, (size_t)B_SZ * K_CB * HW * sizeof(float), s_aux);
    cudaMemsetAsync(out + OFF_HIST, 0, (size_t)B_SZ * K_CB * sizeof(float), s_aux);
    cudaEventRecord(e_join, s_aux);

    // norms + init (one thread per row, sequential chain)
    {
        int rows = K_CB + N_PTS;
        int blocks = (rows + 255) / 256;
        norms_kernel<<<blocks, 256>>>(z, cb);
    }

    // two dummies so the GEMM is launch index 5 (ncu -s 5 -c 1 captures it)
    dummy_kernel<<<1, 32>>>();
    dummy_kernel<<<1, 32>>>();

    // fused GEMM + distance + argmin
    {
        cudaFuncSetAttribute(gemm_kernel, cudaFuncAttributeMaxDynamicSharedMemorySize,
                             GEMM_SMEM_BYTES);
        dim3 grid(N_PTS / 128, K_CB / 64);
        gemm_kernel<<<grid, 256, GEMM_SMEM_BYTES>>>(z, cb);
    }

    // Join: memsets must complete before point_kernel scatters into onehot/hist
    cudaStreamWaitEvent(0, e_join, 0);

    // per-point pass (warp-per-point; argmin precomputed)
    {
        cudaFuncSetAttribute(point_kernel, cudaFuncAttributeMaxDynamicSharedMemorySize,
                             POINT_SMEM_BYTES);
        point_kernel<<<N_PTS / 64, 256, POINT_SMEM_BYTES>>>(z, cb, out);
    }

    // scalars
    finalize_kernel<<<1, 256>>>(out);
}